// round 4
// baseline (speedup 1.0000x reference)
#include <cuda_runtime.h>
#include <cstddef>

#define NN 50000
#define NE 800000
#define FIN 128
#define H1 100
#define H2 200
#define FOUT 16
#define C4_H1 (H1 / 4)          // 25 float4 chunks per row
#define NB ((NN + 255) / 256)   // scan blocks = 196

// -------- scratch (static device globals; no allocation) --------
__device__ __align__(16) int   g_deg[NN];        // edge-only in-degree
__device__ __align__(16) float g_dis[NN];        // (deg+1)^-1/2
__device__ __align__(16) int   g_off[NN];        // CSR offsets (exclusive scan)
__device__ __align__(16) int   g_cur[NN];        // fill cursors
__device__ __align__(16) int   g_bsum[256];      // scan block sums
__device__ __align__(16) int   g_src[NE];        // CSR: source node per slot
__device__ __align__(16) float g_y1 [(size_t)NN * H1];
__device__ __align__(16) float g_s1 [(size_t)NN * H1];
__device__ __align__(16) float g_y2 [(size_t)NN * H1];
__device__ __align__(16) float g_s2 [(size_t)NN * H1];
__device__ __align__(16) float g_xw2[(size_t)NN * H2];

// ================= degree / normalization / CSR =================
__global__ void k_zero_deg(int n) {
    int i = blockIdx.x * blockDim.x + threadIdx.x;
    if (i < n) g_deg[i] = 0;
}

__global__ void k_count_deg(const int* __restrict__ col, int nE) {
    int i = blockIdx.x * blockDim.x + threadIdx.x;
    if (i < nE) {
        int t = col[i];
        if ((unsigned)t < (unsigned)NN) atomicAdd(&g_deg[t], 1);
    }
}

__global__ void k_dis(int n) {
    int i = blockIdx.x * blockDim.x + threadIdx.x;
    if (i < n) g_dis[i] = rsqrtf((float)(g_deg[i] + 1));  // +1 self loop
}

// scan phase 1: per-block sums of deg
__global__ void k_blocksum(int n) {
    __shared__ int sh[256];
    int tid = threadIdx.x;
    int i = blockIdx.x * 256 + tid;
    sh[tid] = (i < n) ? g_deg[i] : 0;
    __syncthreads();
    for (int s = 128; s > 0; s >>= 1) {
        if (tid < s) sh[tid] += sh[tid + s];
        __syncthreads();
    }
    if (tid == 0) g_bsum[blockIdx.x] = sh[0];
}

// scan phase 2: exclusive scan of block sums (single block, 256 threads)
__global__ void k_scan_bsum(int nB) {
    __shared__ int sh[256];
    int tid = threadIdx.x;
    int v = (tid < nB) ? g_bsum[tid] : 0;
    sh[tid] = v;
    __syncthreads();
    for (int off = 1; off < 256; off <<= 1) {
        int t = (tid >= off) ? sh[tid - off] : 0;
        __syncthreads();
        sh[tid] += t;
        __syncthreads();
    }
    if (tid < nB) g_bsum[tid] = sh[tid] - v;  // exclusive
}

// scan phase 3: per-block exclusive scan + block offset -> csr offsets + cursors
__global__ void k_scan_off(int n) {
    __shared__ int sh[256];
    int tid = threadIdx.x;
    int i = blockIdx.x * 256 + tid;
    int v = (i < n) ? g_deg[i] : 0;
    sh[tid] = v;
    __syncthreads();
    for (int off = 1; off < 256; off <<= 1) {
        int t = (tid >= off) ? sh[tid - off] : 0;
        __syncthreads();
        sh[tid] += t;
        __syncthreads();
    }
    if (i < n) {
        int excl = sh[tid] - v + g_bsum[blockIdx.x];
        g_off[i] = excl;
        g_cur[i] = excl;
    }
}

// CSR fill: slot per (target,edge) via atomic cursor
__global__ void k_fill(const int* __restrict__ row, const int* __restrict__ col, int nE) {
    int i = blockIdx.x * blockDim.x + threadIdx.x;
    if (i >= nE) return;
    int r = row[i], t = col[i];
    if ((unsigned)r >= (unsigned)NN || (unsigned)t >= (unsigned)NN) return;
    int slot = atomicAdd(&g_cur[t], 1);
    g_src[slot] = r;
}

// ================= dense layer =================
// out[r][j] = f_in(in[r]) . W[:,j] (+bias) (optional out-scale by dis[r])
template <int K, int N, int G, int RPB, int IN_MODE, int OUT_SCALE>
__global__ void k_dense(const float* __restrict__ in, const float* __restrict__ W,
                        const float* __restrict__ bias, float* __restrict__ out,
                        int nRows) {
    constexpr int ROWS = G * RPB;
    __shared__ __align__(16) float s_in[ROWS][K];

    int r0  = blockIdx.x * ROWS;
    int tid = threadIdx.y * N + threadIdx.x;
    int nth = N * G;

    for (int i = tid; i < ROWS * K; i += nth) {
        int r = i / K;
        int k = i - r * K;
        int gr = r0 + r;
        float v = 0.f;
        if (gr < nRows) {
            v = in[(size_t)gr * K + k];
            if (IN_MODE == 1) v = fmaxf(v, 0.f);
            if (IN_MODE == 2) v *= g_dis[gr];
        }
        s_in[r][k] = v;
    }
    __syncthreads();

    int j     = threadIdx.x;
    int rbase = threadIdx.y * RPB;

    float acc[RPB];
#pragma unroll
    for (int r = 0; r < RPB; r++) acc[r] = 0.f;

#pragma unroll 4
    for (int k0 = 0; k0 < K; k0 += 4) {
        float w0 = __ldg(&W[(size_t)(k0 + 0) * N + j]);
        float w1 = __ldg(&W[(size_t)(k0 + 1) * N + j]);
        float w2 = __ldg(&W[(size_t)(k0 + 2) * N + j]);
        float w3 = __ldg(&W[(size_t)(k0 + 3) * N + j]);
#pragma unroll
        for (int r = 0; r < RPB; r++) {
            float4 a = *(const float4*)&s_in[rbase + r][k0];
            acc[r] = fmaf(a.x, w0, fmaf(a.y, w1, fmaf(a.z, w2, fmaf(a.w, w3, acc[r]))));
        }
    }

    float b = (bias != nullptr) ? __ldg(&bias[j]) : 0.f;
#pragma unroll
    for (int r = 0; r < RPB; r++) {
        int gr = r0 + rbase + r;
        if (gr < nRows) {
            float v = acc[r] + b;
            if (OUT_SCALE) v *= g_dis[gr];
            out[(size_t)gr * N + j] = v;
        }
    }
}

// ================= CSR gather aggregation =================
// s[i] = y[i] (self loop) + sum_{neighbors r} y[r]. Warp per node, lane = chunk.
__global__ void k_agg_csr(const float4* __restrict__ y, float4* __restrict__ s, int nN) {
    int node = blockIdx.x * blockDim.y + threadIdx.y;
    if (node >= nN) return;
    int lane = threadIdx.x;
    int start = g_off[node];
    int cnt   = g_deg[node];

    float4 acc = make_float4(0.f, 0.f, 0.f, 0.f);
    if (lane < C4_H1) acc = y[(size_t)node * C4_H1 + lane];

    for (int k = 0; k < cnt; k += 32) {
        int idx  = start + k + lane;
        int r_my = (k + lane < cnt) ? g_src[idx] : 0;
        int m = min(32, cnt - k);
#pragma unroll 4
        for (int j = 0; j < m; j++) {
            int r = __shfl_sync(0xffffffffu, r_my, j);
            if (lane < C4_H1) {
                float4 v = __ldg(&y[(size_t)r * C4_H1 + lane]);
                acc.x += v.x; acc.y += v.y; acc.z += v.z; acc.w += v.w;
            }
        }
    }
    if (lane < C4_H1) s[(size_t)node * C4_H1 + lane] = acc;
}

// ================= mid elementwise: y2 = d * relu(d*S1 + b1) =================
__global__ void k_mid(const float4* __restrict__ S1, const float* __restrict__ b1,
                      float4* __restrict__ Y2, int nRows) {
    int idx = blockIdx.x * blockDim.x + threadIdx.x;
    int total = nRows * C4_H1;
    if (idx >= total) return;
    int i = idx / C4_H1;
    int c = idx - i * C4_H1;
    float d  = g_dis[i];
    float4 s = S1[idx];
    float4 b = *(const float4*)&b1[c * 4];
    float4 v;
    v.x = d * fmaxf(fmaf(d, s.x, b.x), 0.f);
    v.y = d * fmaxf(fmaf(d, s.y, b.y), 0.f);
    v.z = d * fmaxf(fmaf(d, s.z, b.z), 0.f);
    v.w = d * fmaxf(fmaf(d, s.w, b.w), 0.f);
    Y2[idx] = v;
}

// ================= launch =================
extern "C" void kernel_launch(void* const* d_in, const int* in_sizes, int n_in,
                              void* d_out, int out_size) {
    const float* x   = (const float*)d_in[0];   // [NN, FIN]
    const int*   ei  = (const int*)d_in[1];     // [2, NE] int32
    const float* W1  = (const float*)d_in[2];
    const float* b1  = (const float*)d_in[3];
    const float* W2  = (const float*)d_in[4];
    const float* b2  = (const float*)d_in[5];
    const float* Wfc = (const float*)d_in[6];
    const float* bfc = (const float*)d_in[7];
    float*       out = (float*)d_out;

    int nN = in_sizes[0] / FIN;
    int nE = in_sizes[1] / 2;
    const int* rowI = ei;
    const int* colI = ei + nE;

    float *p_y1, *p_s1, *p_y2, *p_s2, *p_xw2;
    cudaGetSymbolAddress((void**)&p_y1,  g_y1);
    cudaGetSymbolAddress((void**)&p_s1,  g_s1);
    cudaGetSymbolAddress((void**)&p_y2,  g_y2);
    cudaGetSymbolAddress((void**)&p_s2,  g_s2);
    cudaGetSymbolAddress((void**)&p_xw2, g_xw2);

    int nB = (nN + 255) / 256;

    // --- degree, normalization, CSR build ---
    k_zero_deg <<<nB, 256>>>(nN);
    k_count_deg<<<(nE + 255) / 256, 256>>>(colI, nE);
    k_dis      <<<nB, 256>>>(nN);
    k_blocksum <<<nB, 256>>>(nN);
    k_scan_bsum<<<1, 256>>>(nB);
    k_scan_off <<<nB, 256>>>(nN);
    k_fill     <<<(nE + 255) / 256, 256>>>(rowI, colI, nE);

    // --- layer 1 ---
    // y1 = d_r ⊙ (x @ W1)
    k_dense<FIN, H1, 4, 8, 0, 1><<<(nN + 31) / 32, dim3(H1, 4)>>>(x, W1, nullptr, p_y1, nN);
    // s1 = y1_self + gather
    k_agg_csr<<<(nN + 7) / 8, dim3(32, 8)>>>((const float4*)p_y1, (float4*)p_s1, nN);

    // --- mid: y2 = d ⊙ relu(d ⊙ s1 + b1)  (layer-2 agg commuted before GEMM) ---
    {
        int work = nN * C4_H1;
        k_mid<<<(work + 255) / 256, 256>>>((const float4*)p_s1, b1, (float4*)p_y2, nN);
    }

    // s2 = y2_self + gather (100-wide)
    k_agg_csr<<<(nN + 7) / 8, dim3(32, 8)>>>((const float4*)p_y2, (float4*)p_s2, nN);

    // --- layer 2 GEMM: xw2 = (d ⊙ s2) @ W2 + b2 ---
    k_dense<H1, H2, 2, 8, 2, 0><<<(nN + 15) / 16, dim3(H2, 2)>>>(p_s2, W2, b2, p_xw2, nN);

    // --- FC: out = relu(xw2) @ Wfc + bfc ---
    k_dense<H2, FOUT, 4, 8, 1, 0><<<(nN + 31) / 32, dim3(FOUT, 4)>>>(p_xw2, Wfc, bfc, out, nN);
}

// round 5
// speedup vs baseline: 1.1670x; 1.1670x over previous
#include <cuda_runtime.h>
#include <cstddef>

#define NN 50000
#define FIN 128
#define H1 100
#define H2 200
#define FOUT 16
#define C4_H1 (H1 / 4)   // 25 float4 chunks per row

// -------- scratch (static device globals; no allocation) --------
__device__ __align__(16) int   g_deg[NN];
__device__ __align__(16) float g_dis[NN];
__device__ __align__(16) float g_y1 [(size_t)NN * H1];  // d_r * (x @ W1)
__device__ __align__(16) float g_s1 [(size_t)NN * H1];  // scatter accumulator 1
__device__ __align__(16) float g_y2 [(size_t)NN * H1];  // d_i * relu(d_i*S1 + b1)
__device__ __align__(16) float g_s2 [(size_t)NN * H1];  // scatter accumulator 2
__device__ __align__(16) float g_xw2[(size_t)NN * H2];  // (d ⊙ S2) @ W2 + b2

// -------- degree / normalization --------
__global__ void k_init_deg(int n) {
    int i = blockIdx.x * blockDim.x + threadIdx.x;
    if (i < n) g_deg[i] = 1;  // self loop
}

__global__ void k_count_deg(const int* __restrict__ col, int nE) {
    int i = blockIdx.x * blockDim.x + threadIdx.x;
    if (i < nE) {
        int t = col[i];
        if ((unsigned)t < (unsigned)NN) atomicAdd(&g_deg[t], 1);
    }
}

__global__ void k_dis(int n) {
    int i = blockIdx.x * blockDim.x + threadIdx.x;
    if (i < n) g_dis[i] = rsqrtf((float)g_deg[i]);
}

// -------- dense layer: out[r][j] = f_in(in[r]) . W[:,j] (+bias) --------
// IN_MODE: 0=plain, 1=relu, 2=scale by dis[row].  OUT_SCALE: multiply by dis[row].
// blockDim = (N, G); each y-group handles RPB rows; optional dual write (out2).
template <int K, int N, int G, int RPB, int IN_MODE, int OUT_SCALE>
__global__ void k_dense(const float* __restrict__ in, const float* __restrict__ W,
                        const float* __restrict__ bias, float* __restrict__ out,
                        float* __restrict__ out2, int nRows) {
    constexpr int ROWS = G * RPB;
    __shared__ __align__(16) float s_in[ROWS][K];

    int r0  = blockIdx.x * ROWS;
    int tid = threadIdx.y * N + threadIdx.x;
    int nth = N * G;

    for (int i = tid; i < ROWS * K; i += nth) {
        int r = i / K;
        int k = i - r * K;
        int gr = r0 + r;
        float v = 0.f;
        if (gr < nRows) {
            v = in[(size_t)gr * K + k];
            if (IN_MODE == 1) v = fmaxf(v, 0.f);
            if (IN_MODE == 2) v *= g_dis[gr];
        }
        s_in[r][k] = v;
    }
    __syncthreads();

    int j     = threadIdx.x;
    int rbase = threadIdx.y * RPB;

    float acc[RPB];
#pragma unroll
    for (int r = 0; r < RPB; r++) acc[r] = 0.f;

#pragma unroll 4
    for (int k0 = 0; k0 < K; k0 += 4) {
        float w0 = __ldg(&W[(size_t)(k0 + 0) * N + j]);
        float w1 = __ldg(&W[(size_t)(k0 + 1) * N + j]);
        float w2 = __ldg(&W[(size_t)(k0 + 2) * N + j]);
        float w3 = __ldg(&W[(size_t)(k0 + 3) * N + j]);
#pragma unroll
        for (int r = 0; r < RPB; r++) {
            float4 a = *(const float4*)&s_in[rbase + r][k0];
            acc[r] = fmaf(a.x, w0, fmaf(a.y, w1, fmaf(a.z, w2, fmaf(a.w, w3, acc[r]))));
        }
    }

    float b = (bias != nullptr) ? __ldg(&bias[j]) : 0.f;
#pragma unroll
    for (int r = 0; r < RPB; r++) {
        int gr = r0 + rbase + r;
        if (gr < nRows) {
            float v = acc[r] + b;
            if (OUT_SCALE) v *= g_dis[gr];
            out[(size_t)gr * N + j] = v;
            if (out2 != nullptr) out2[(size_t)gr * N + j] = v;
        }
    }
}

// -------- pure edge scatter-add: dst[t] += src[r], float4 chunks --------
template <int C4>
__global__ void k_edge_agg(const float4* __restrict__ src4, float* __restrict__ dst,
                           const int* __restrict__ rowIdx,
                           const int* __restrict__ colIdx, int nE) {
    int idx = blockIdx.x * blockDim.x + threadIdx.x;
    int total = nE * C4;
    if (idx >= total) return;
    int e = idx / C4;
    int c = idx - e * C4;
    int r = rowIdx[e];
    int t = colIdx[e];
    if ((unsigned)r >= (unsigned)NN || (unsigned)t >= (unsigned)NN) return;
    float4 v = src4[(size_t)r * C4 + c];
    float* p = dst + ((size_t)t * C4 + c) * 4;
    asm volatile("red.global.add.v4.f32 [%0], {%1,%2,%3,%4};"
                 :: "l"(p), "f"(v.x), "f"(v.y), "f"(v.z), "f"(v.w)
                 : "memory");
}

// -------- mid elementwise: y2 = d * relu(d*S1 + b1); write to y2 and s2 --------
__global__ void k_mid(const float4* __restrict__ S1, const float* __restrict__ b1,
                      float4* __restrict__ Y2, float4* __restrict__ S2, int nRows) {
    int idx = blockIdx.x * blockDim.x + threadIdx.x;
    int total = nRows * C4_H1;
    if (idx >= total) return;
    int i = idx / C4_H1;
    int c = idx - i * C4_H1;
    float d  = g_dis[i];
    float4 s = S1[idx];
    float4 b = *(const float4*)&b1[c * 4];
    float4 v;
    v.x = d * fmaxf(fmaf(d, s.x, b.x), 0.f);
    v.y = d * fmaxf(fmaf(d, s.y, b.y), 0.f);
    v.z = d * fmaxf(fmaf(d, s.z, b.z), 0.f);
    v.w = d * fmaxf(fmaf(d, s.w, b.w), 0.f);
    Y2[idx] = v;
    S2[idx] = v;
}

// -------- launch --------
extern "C" void kernel_launch(void* const* d_in, const int* in_sizes, int n_in,
                              void* d_out, int out_size) {
    const float* x   = (const float*)d_in[0];   // [NN, FIN]
    const int*   ei  = (const int*)d_in[1];     // [2, NE] int32
    const float* W1  = (const float*)d_in[2];
    const float* b1  = (const float*)d_in[3];
    const float* W2  = (const float*)d_in[4];
    const float* b2  = (const float*)d_in[5];
    const float* Wfc = (const float*)d_in[6];
    const float* bfc = (const float*)d_in[7];
    float*       out = (float*)d_out;

    int nN = in_sizes[0] / FIN;
    int nE = in_sizes[1] / 2;
    const int* rowI = ei;
    const int* colI = ei + nE;

    float *p_y1, *p_s1, *p_y2, *p_s2, *p_xw2;
    cudaGetSymbolAddress((void**)&p_y1,  g_y1);
    cudaGetSymbolAddress((void**)&p_s1,  g_s1);
    cudaGetSymbolAddress((void**)&p_y2,  g_y2);
    cudaGetSymbolAddress((void**)&p_s2,  g_s2);
    cudaGetSymbolAddress((void**)&p_xw2, g_xw2);

    // 1) degree (with self loops) and dis = deg^-1/2
    k_init_deg<<<(nN + 255) / 256, 256>>>(nN);
    k_count_deg<<<(nE + 255) / 256, 256>>>(colI, nE);
    k_dis<<<(nN + 255) / 256, 256>>>(nN);

    // 2) Y1 = d_r ⊙ (x @ W1); S1 initialized to the same (self-loop term)
    k_dense<FIN, H1, 4, 8, 0, 1><<<(nN + 31) / 32, dim3(H1, 4)>>>(
        x, W1, nullptr, p_y1, p_s1, nN);

    // 3) S1[t] += Σ_edges Y1[r]   (pure scatter)
    {
        int work = nE * C4_H1;
        k_edge_agg<C4_H1><<<(work + 255) / 256, 256>>>(
            (const float4*)p_y1, p_s1, rowI, colI, nE);
    }

    // 4) Y2 = d ⊙ relu(d ⊙ S1 + b1); S2 = same (layer-2 agg commuted before GEMM)
    {
        int work = nN * C4_H1;
        k_mid<<<(work + 255) / 256, 256>>>(
            (const float4*)p_s1, b1, (float4*)p_y2, (float4*)p_s2, nN);
    }

    // 5) S2[t] += Σ_edges Y2[r]   (100-wide)
    {
        int work = nE * C4_H1;
        k_edge_agg<C4_H1><<<(work + 255) / 256, 256>>>(
            (const float4*)p_y2, p_s2, rowI, colI, nE);
    }

    // 6) XW2 = (d ⊙ S2) @ W2 + b2
    k_dense<H1, H2, 2, 8, 2, 0><<<(nN + 15) / 16, dim3(H2, 2)>>>(
        p_s2, W2, b2, p_xw2, nullptr, nN);

    // 7) out = relu(XW2) @ Wfc + bfc
    k_dense<H2, FOUT, 8, 8, 1, 0><<<(nN + 63) / 64, dim3(FOUT, 8)>>>(
        p_xw2, Wfc, bfc, out, nullptr, nN);
}

// round 6
// speedup vs baseline: 1.2514x; 1.0723x over previous
#include <cuda_runtime.h>
#include <cstddef>

#define NN 50000
#define FIN 128
#define H1 100
#define H2 200
#define FOUT 16
#define C4_H1 (H1 / 4)   // 25 float4 chunks per row

// -------- scratch (static device globals; no allocation) --------
__device__ __align__(16) int   g_deg[NN];
__device__ __align__(16) float g_dis[NN];
__device__ __align__(16) float g_y1 [(size_t)NN * H1];
__device__ __align__(16) float g_s1 [(size_t)NN * H1];
__device__ __align__(16) float g_y2 [(size_t)NN * H1];
__device__ __align__(16) float g_s2 [(size_t)NN * H1];
__device__ __align__(16) float g_xw2[(size_t)NN * H2];

// -------- degree / normalization --------
__global__ void k_init_deg(int n) {
    int i = blockIdx.x * blockDim.x + threadIdx.x;
    if (i < n) g_deg[i] = 1;  // self loop
}
__global__ void k_count_deg(const int* __restrict__ col, int nE) {
    int i = blockIdx.x * blockDim.x + threadIdx.x;
    if (i < nE) {
        int t = col[i];
        if ((unsigned)t < (unsigned)NN) atomicAdd(&g_deg[t], 1);
    }
}
__global__ void k_dis(int n) {
    int i = blockIdx.x * blockDim.x + threadIdx.x;
    if (i < n) g_dis[i] = rsqrtf((float)g_deg[i]);
}

// ======== warp-aligned dense: block (32, WARPS); lane owns NJ cols; warp owns RPW rows ========
// IN_MODE: 0=plain, 1=relu, 2=scale by dis[row].  OUT_SCALE: multiply by dis[row].
template <int K, int N, int NJ, int RPW, int WARPS, int IN_MODE, int OUT_SCALE>
__global__ void __launch_bounds__(WARPS * 32)
k_dense_w(const float* __restrict__ in, const float* __restrict__ W,
          const float* __restrict__ bias, float* __restrict__ out,
          float* __restrict__ out2, int nRows) {
    constexpr int ROWS = WARPS * RPW;
    constexpr int KV = K / 4;
    __shared__ __align__(16) float s_in[ROWS][K];

    int r0  = blockIdx.x * ROWS;
    int tid = threadIdx.y * 32 + threadIdx.x;
    constexpr int NTH = WARPS * 32;

    // cooperative vectorized tile load (+ fused input transform)
    const float4* in4 = (const float4*)in;
    for (int i = tid; i < ROWS * KV; i += NTH) {
        int r = i / KV;
        int c = i - r * KV;
        int gr = r0 + r;
        float4 v = make_float4(0.f, 0.f, 0.f, 0.f);
        if (gr < nRows) {
            v = in4[(size_t)gr * KV + c];
            if (IN_MODE == 1) {
                v.x = fmaxf(v.x, 0.f); v.y = fmaxf(v.y, 0.f);
                v.z = fmaxf(v.z, 0.f); v.w = fmaxf(v.w, 0.f);
            }
            if (IN_MODE == 2) {
                float d = g_dis[gr];
                v.x *= d; v.y *= d; v.z *= d; v.w *= d;
            }
        }
        *(float4*)&s_in[r][c * 4] = v;
    }
    __syncthreads();

    int lane  = threadIdx.x;
    int rbase = threadIdx.y * RPW;

    float acc[RPW][NJ];
#pragma unroll
    for (int r = 0; r < RPW; r++)
#pragma unroll
        for (int jj = 0; jj < NJ; jj++) acc[r][jj] = 0.f;

#pragma unroll 2
    for (int k0 = 0; k0 < K; k0 += 4) {
        float wr[4][NJ];
#pragma unroll
        for (int kk = 0; kk < 4; kk++)
#pragma unroll
            for (int jj = 0; jj < NJ; jj++) {
                int j = lane + jj * 32;
                wr[kk][jj] = (j < N) ? __ldg(&W[(size_t)(k0 + kk) * N + j]) : 0.f;
            }
#pragma unroll
        for (int r = 0; r < RPW; r++) {
            float4 a = *(const float4*)&s_in[rbase + r][k0];  // warp broadcast
#pragma unroll
            for (int jj = 0; jj < NJ; jj++)
                acc[r][jj] = fmaf(a.x, wr[0][jj], fmaf(a.y, wr[1][jj],
                             fmaf(a.z, wr[2][jj], fmaf(a.w, wr[3][jj], acc[r][jj]))));
        }
    }

    float bv[NJ];
#pragma unroll
    for (int jj = 0; jj < NJ; jj++) {
        int j = lane + jj * 32;
        bv[jj] = (bias != nullptr && j < N) ? __ldg(&bias[j]) : 0.f;
    }
#pragma unroll
    for (int r = 0; r < RPW; r++) {
        int gr = r0 + rbase + r;
        if (gr < nRows) {
            float d = OUT_SCALE ? g_dis[gr] : 1.f;
#pragma unroll
            for (int jj = 0; jj < NJ; jj++) {
                int j = lane + jj * 32;
                if (j < N) {
                    float v = (acc[r][jj] + bv[jj]) * d;
                    out[(size_t)gr * N + j] = v;
                    if (out2 != nullptr) out2[(size_t)gr * N + j] = v;
                }
            }
        }
    }
}

// ======== old-style dense (kept for FC: N=16 divides warps cleanly) ========
template <int K, int N, int G, int RPB, int IN_MODE>
__global__ void k_dense(const float* __restrict__ in, const float* __restrict__ W,
                        const float* __restrict__ bias, float* __restrict__ out,
                        int nRows) {
    constexpr int ROWS = G * RPB;
    __shared__ __align__(16) float s_in[ROWS][K];

    int r0  = blockIdx.x * ROWS;
    int tid = threadIdx.y * N + threadIdx.x;
    int nth = N * G;

    for (int i = tid; i < ROWS * K; i += nth) {
        int r = i / K;
        int k = i - r * K;
        int gr = r0 + r;
        float v = 0.f;
        if (gr < nRows) {
            v = in[(size_t)gr * K + k];
            if (IN_MODE == 1) v = fmaxf(v, 0.f);
        }
        s_in[r][k] = v;
    }
    __syncthreads();

    int j     = threadIdx.x;
    int rbase = threadIdx.y * RPB;

    float acc[RPB];
#pragma unroll
    for (int r = 0; r < RPB; r++) acc[r] = 0.f;

#pragma unroll 4
    for (int k0 = 0; k0 < K; k0 += 4) {
        float w0 = __ldg(&W[(size_t)(k0 + 0) * N + j]);
        float w1 = __ldg(&W[(size_t)(k0 + 1) * N + j]);
        float w2 = __ldg(&W[(size_t)(k0 + 2) * N + j]);
        float w3 = __ldg(&W[(size_t)(k0 + 3) * N + j]);
#pragma unroll
        for (int r = 0; r < RPB; r++) {
            float4 a = *(const float4*)&s_in[rbase + r][k0];
            acc[r] = fmaf(a.x, w0, fmaf(a.y, w1, fmaf(a.z, w2, fmaf(a.w, w3, acc[r]))));
        }
    }

    float b = (bias != nullptr) ? __ldg(&bias[j]) : 0.f;
#pragma unroll
    for (int r = 0; r < RPB; r++) {
        int gr = r0 + rbase + r;
        if (gr < nRows) out[(size_t)gr * N + j] = acc[r] + b;
    }
}

// -------- pure edge scatter-add: dst[t] += src[r], float4 chunks --------
template <int C4>
__global__ void k_edge_agg(const float4* __restrict__ src4, float* __restrict__ dst,
                           const int* __restrict__ rowIdx,
                           const int* __restrict__ colIdx, int nE) {
    int idx = blockIdx.x * blockDim.x + threadIdx.x;
    int total = nE * C4;
    if (idx >= total) return;
    int e = idx / C4;
    int c = idx - e * C4;
    int r = rowIdx[e];
    int t = colIdx[e];
    if ((unsigned)r >= (unsigned)NN || (unsigned)t >= (unsigned)NN) return;
    float4 v = src4[(size_t)r * C4 + c];
    float* p = dst + ((size_t)t * C4 + c) * 4;
    asm volatile("red.global.add.v4.f32 [%0], {%1,%2,%3,%4};"
                 :: "l"(p), "f"(v.x), "f"(v.y), "f"(v.z), "f"(v.w)
                 : "memory");
}

// -------- mid elementwise: y2 = d * relu(d*S1 + b1); write to y2 and s2 --------
__global__ void k_mid(const float4* __restrict__ S1, const float* __restrict__ b1,
                      float4* __restrict__ Y2, float4* __restrict__ S2, int nRows) {
    int idx = blockIdx.x * blockDim.x + threadIdx.x;
    int total = nRows * C4_H1;
    if (idx >= total) return;
    int i = idx / C4_H1;
    int c = idx - i * C4_H1;
    float d  = g_dis[i];
    float4 s = S1[idx];
    float4 b = *(const float4*)&b1[c * 4];
    float4 v;
    v.x = d * fmaxf(fmaf(d, s.x, b.x), 0.f);
    v.y = d * fmaxf(fmaf(d, s.y, b.y), 0.f);
    v.z = d * fmaxf(fmaf(d, s.z, b.z), 0.f);
    v.w = d * fmaxf(fmaf(d, s.w, b.w), 0.f);
    Y2[idx] = v;
    S2[idx] = v;
}

// -------- launch --------
extern "C" void kernel_launch(void* const* d_in, const int* in_sizes, int n_in,
                              void* d_out, int out_size) {
    const float* x   = (const float*)d_in[0];   // [NN, FIN]
    const int*   ei  = (const int*)d_in[1];     // [2, NE] int32
    const float* W1  = (const float*)d_in[2];
    const float* b1  = (const float*)d_in[3];
    const float* W2  = (const float*)d_in[4];
    const float* b2  = (const float*)d_in[5];
    const float* Wfc = (const float*)d_in[6];
    const float* bfc = (const float*)d_in[7];
    float*       out = (float*)d_out;

    int nN = in_sizes[0] / FIN;
    int nE = in_sizes[1] / 2;
    const int* rowI = ei;
    const int* colI = ei + nE;

    float *p_y1, *p_s1, *p_y2, *p_s2, *p_xw2;
    cudaGetSymbolAddress((void**)&p_y1,  g_y1);
    cudaGetSymbolAddress((void**)&p_s1,  g_s1);
    cudaGetSymbolAddress((void**)&p_y2,  g_y2);
    cudaGetSymbolAddress((void**)&p_s2,  g_s2);
    cudaGetSymbolAddress((void**)&p_xw2, g_xw2);

    // 1) degree (with self loops) and dis = deg^-1/2
    k_init_deg<<<(nN + 255) / 256, 256>>>(nN);
    k_count_deg<<<(nE + 255) / 256, 256>>>(colI, nE);
    k_dis<<<(nN + 255) / 256, 256>>>(nN);

    // 2) Y1 = d_r ⊙ (x @ W1); S1 initialized to same (self-loop term)
    k_dense_w<FIN, H1, 4, 8, 8, 0, 1><<<(nN + 63) / 64, dim3(32, 8)>>>(
        x, W1, nullptr, p_y1, p_s1, nN);

    // 3) S1[t] += Σ_edges Y1[r]
    {
        int work = nE * C4_H1;
        k_edge_agg<C4_H1><<<(work + 255) / 256, 256>>>(
            (const float4*)p_y1, p_s1, rowI, colI, nE);
    }

    // 4) Y2 = d ⊙ relu(d ⊙ S1 + b1); S2 = same
    {
        int work = nN * C4_H1;
        k_mid<<<(work + 255) / 256, 256>>>(
            (const float4*)p_s1, b1, (float4*)p_y2, (float4*)p_s2, nN);
    }

    // 5) S2[t] += Σ_edges Y2[r]
    {
        int work = nE * C4_H1;
        k_edge_agg<C4_H1><<<(work + 255) / 256, 256>>>(
            (const float4*)p_y2, p_s2, rowI, colI, nE);
    }

    // 6) XW2 = (d ⊙ S2) @ W2 + b2
    k_dense_w<H1, H2, 7, 8, 8, 2, 0><<<(nN + 63) / 64, dim3(32, 8)>>>(
        p_s2, W2, b2, p_xw2, nullptr, nN);

    // 7) out = relu(XW2) @ Wfc + bfc   (N=16: old kernel is warp-aligned here)
    k_dense<H2, FOUT, 8, 4, 1><<<(nN + 31) / 32, dim3(FOUT, 8)>>>(
        p_xw2, Wfc, bfc, out, nN);
}

// round 7
// speedup vs baseline: 1.6748x; 1.3384x over previous
#include <cuda_runtime.h>
#include <cstddef>

#define NN 50000
#define NE_MAX 800000
#define FIN 128
#define H1 100
#define H2 200
#define FOUT 16
#define C4_H1 (H1 / 4)   // 25 float4 chunks per row

// -------- scratch (static device globals; no allocation) --------
__device__ __align__(16) int   g_deg[NN];     // edge-only in-degree
__device__ __align__(16) float g_dis[NN];     // (deg+1)^-1/2
__device__ __align__(16) int   g_off[NN];     // CSR range start (arbitrary order)
__device__ __align__(16) int   g_cur[NN];     // fill cursors
__device__            int   g_total;          // global slot cursor
__device__ __align__(16) int   g_src[NE_MAX]; // CSR: source node per slot
__device__ __align__(16) float g_y1 [(size_t)NN * H1];
__device__ __align__(16) float g_y2 [(size_t)NN * H1];
__device__ __align__(16) float g_s2 [(size_t)NN * H1];  // d ⊙ (agg2)
__device__ __align__(16) float g_xw2[(size_t)NN * H2];

// ================= degree / CSR build =================
__global__ void k_zero_deg(int n) {
    int i = blockIdx.x * blockDim.x + threadIdx.x;
    if (i < n) g_deg[i] = 0;
    if (i == 0) g_total = 0;
}

__global__ void k_count_deg(const int* __restrict__ col, int nE) {
    int i = blockIdx.x * blockDim.x + threadIdx.x;
    if (i < nE) {
        int t = col[i];
        if ((unsigned)t < (unsigned)NN) atomicAdd(&g_deg[t], 1);
    }
}

// dis = (deg+1)^-1/2 ; CSR range via global cursor (order irrelevant)
__global__ void k_assign(int n) {
    int i = blockIdx.x * blockDim.x + threadIdx.x;
    if (i >= n) return;
    int d = g_deg[i];
    g_dis[i] = rsqrtf((float)(d + 1));
    int off = atomicAdd(&g_total, d);
    g_off[i] = off;
    g_cur[i] = off;
}

__global__ void k_fill(const int* __restrict__ row, const int* __restrict__ col, int nE) {
    int i = blockIdx.x * blockDim.x + threadIdx.x;
    if (i >= nE) return;
    int r = row[i], t = col[i];
    if ((unsigned)r >= (unsigned)NN || (unsigned)t >= (unsigned)NN) return;
    int slot = atomicAdd(&g_cur[t], 1);
    g_src[slot] = r;
}

// ================= warp-aligned dense =================
// IN_MODE: 0=plain, 1=relu.  OUT_SCALE: multiply by dis[row].
template <int K, int N, int NJ, int RPW, int WARPS, int IN_MODE, int OUT_SCALE>
__global__ void __launch_bounds__(WARPS * 32)
k_dense_w(const float* __restrict__ in, const float* __restrict__ W,
          const float* __restrict__ bias, float* __restrict__ out, int nRows) {
    constexpr int ROWS = WARPS * RPW;
    constexpr int KV = K / 4;
    __shared__ __align__(16) float s_in[ROWS][K];

    int r0  = blockIdx.x * ROWS;
    int tid = threadIdx.y * 32 + threadIdx.x;
    constexpr int NTH = WARPS * 32;

    const float4* in4 = (const float4*)in;
    for (int i = tid; i < ROWS * KV; i += NTH) {
        int r = i / KV;
        int c = i - r * KV;
        int gr = r0 + r;
        float4 v = make_float4(0.f, 0.f, 0.f, 0.f);
        if (gr < nRows) {
            v = in4[(size_t)gr * KV + c];
            if (IN_MODE == 1) {
                v.x = fmaxf(v.x, 0.f); v.y = fmaxf(v.y, 0.f);
                v.z = fmaxf(v.z, 0.f); v.w = fmaxf(v.w, 0.f);
            }
        }
        *(float4*)&s_in[r][c * 4] = v;
    }
    __syncthreads();

    int lane  = threadIdx.x;
    int rbase = threadIdx.y * RPW;

    float acc[RPW][NJ];
#pragma unroll
    for (int r = 0; r < RPW; r++)
#pragma unroll
        for (int jj = 0; jj < NJ; jj++) acc[r][jj] = 0.f;

#pragma unroll 2
    for (int k0 = 0; k0 < K; k0 += 4) {
        float wr[4][NJ];
#pragma unroll
        for (int kk = 0; kk < 4; kk++)
#pragma unroll
            for (int jj = 0; jj < NJ; jj++) {
                int j = lane + jj * 32;
                wr[kk][jj] = (j < N) ? __ldg(&W[(size_t)(k0 + kk) * N + j]) : 0.f;
            }
#pragma unroll
        for (int r = 0; r < RPW; r++) {
            float4 a = *(const float4*)&s_in[rbase + r][k0];  // warp broadcast
#pragma unroll
            for (int jj = 0; jj < NJ; jj++)
                acc[r][jj] = fmaf(a.x, wr[0][jj], fmaf(a.y, wr[1][jj],
                             fmaf(a.z, wr[2][jj], fmaf(a.w, wr[3][jj], acc[r][jj]))));
        }
    }

    float bv[NJ];
#pragma unroll
    for (int jj = 0; jj < NJ; jj++) {
        int j = lane + jj * 32;
        bv[jj] = (bias != nullptr && j < N) ? __ldg(&bias[j]) : 0.f;
    }
#pragma unroll
    for (int r = 0; r < RPW; r++) {
        int gr = r0 + rbase + r;
        if (gr < nRows) {
            float d = OUT_SCALE ? g_dis[gr] : 1.f;
#pragma unroll
            for (int jj = 0; jj < NJ; jj++) {
                int j = lane + jj * 32;
                if (j < N) out[(size_t)gr * N + j] = (acc[r][jj] + bv[jj]) * d;
            }
        }
    }
}

// ======== old-style dense (FC: N=16 divides warps cleanly) ========
template <int K, int N, int G, int RPB, int IN_MODE>
__global__ void k_dense(const float* __restrict__ in, const float* __restrict__ W,
                        const float* __restrict__ bias, float* __restrict__ out,
                        int nRows) {
    constexpr int ROWS = G * RPB;
    __shared__ __align__(16) float s_in[ROWS][K];

    int r0  = blockIdx.x * ROWS;
    int tid = threadIdx.y * N + threadIdx.x;
    int nth = N * G;

    for (int i = tid; i < ROWS * K; i += nth) {
        int r = i / K;
        int k = i - r * K;
        int gr = r0 + r;
        float v = 0.f;
        if (gr < nRows) {
            v = in[(size_t)gr * K + k];
            if (IN_MODE == 1) v = fmaxf(v, 0.f);
        }
        s_in[r][k] = v;
    }
    __syncthreads();

    int j     = threadIdx.x;
    int rbase = threadIdx.y * RPB;

    float acc[RPB];
#pragma unroll
    for (int r = 0; r < RPB; r++) acc[r] = 0.f;

#pragma unroll 4
    for (int k0 = 0; k0 < K; k0 += 4) {
        float w0 = __ldg(&W[(size_t)(k0 + 0) * N + j]);
        float w1 = __ldg(&W[(size_t)(k0 + 1) * N + j]);
        float w2 = __ldg(&W[(size_t)(k0 + 2) * N + j]);
        float w3 = __ldg(&W[(size_t)(k0 + 3) * N + j]);
#pragma unroll
        for (int r = 0; r < RPB; r++) {
            float4 a = *(const float4*)&s_in[rbase + r][k0];
            acc[r] = fmaf(a.x, w0, fmaf(a.y, w1, fmaf(a.z, w2, fmaf(a.w, w3, acc[r]))));
        }
    }

    float b = (bias != nullptr) ? __ldg(&bias[j]) : 0.f;
#pragma unroll
    for (int r = 0; r < RPB; r++) {
        int gr = r0 + rbase + r;
        if (gr < nRows) out[(size_t)gr * N + j] = acc[r] + b;
    }
}

// ================= CSR gather aggregation (warp per node) =================
// acc = y[node] + sum_{r in neighbors} y[r]  (coalesced row reads; uniform idx loads)
// MODE 1: out = d * relu(d * acc + bias)   (fused mid transform)
// MODE 2: out = d * acc                    (pre-scale for next GEMM)
template <int C4, int MODE>
__global__ void __launch_bounds__(256)
k_gather(const float4* __restrict__ y, const float* __restrict__ bias,
         float4* __restrict__ out, int nN) {
    int node = blockIdx.x * blockDim.y + threadIdx.y;
    if (node >= nN) return;
    int lane  = threadIdx.x;
    int start = g_off[node];
    int cnt   = g_deg[node];
    bool act  = (lane < C4);

    float4 acc = make_float4(0.f, 0.f, 0.f, 0.f);
    if (act) acc = y[(size_t)node * C4 + lane];

    int j = 0;
    for (; j + 8 <= cnt; j += 8) {
        int rr[8];
#pragma unroll
        for (int u = 0; u < 8; u++) rr[u] = g_src[start + j + u];  // warp-uniform
#pragma unroll
        for (int u = 0; u < 8; u++) {
            if (act) {
                float4 v = __ldg(&y[(size_t)rr[u] * C4 + lane]);
                acc.x += v.x; acc.y += v.y; acc.z += v.z; acc.w += v.w;
            }
        }
    }
    for (; j < cnt; j++) {
        int r = g_src[start + j];
        if (act) {
            float4 v = __ldg(&y[(size_t)r * C4 + lane]);
            acc.x += v.x; acc.y += v.y; acc.z += v.z; acc.w += v.w;
        }
    }

    if (act) {
        float d = g_dis[node];
        float4 o;
        if (MODE == 1) {
            float4 b = *(const float4*)&bias[lane * 4];
            o.x = d * fmaxf(fmaf(d, acc.x, b.x), 0.f);
            o.y = d * fmaxf(fmaf(d, acc.y, b.y), 0.f);
            o.z = d * fmaxf(fmaf(d, acc.z, b.z), 0.f);
            o.w = d * fmaxf(fmaf(d, acc.w, b.w), 0.f);
        } else {
            o.x = d * acc.x; o.y = d * acc.y; o.z = d * acc.z; o.w = d * acc.w;
        }
        out[(size_t)node * C4 + lane] = o;
    }
}

// ================= launch =================
extern "C" void kernel_launch(void* const* d_in, const int* in_sizes, int n_in,
                              void* d_out, int out_size) {
    const float* x   = (const float*)d_in[0];   // [NN, FIN]
    const int*   ei  = (const int*)d_in[1];     // [2, NE] int32
    const float* W1  = (const float*)d_in[2];
    const float* b1  = (const float*)d_in[3];
    const float* W2  = (const float*)d_in[4];
    const float* b2  = (const float*)d_in[5];
    const float* Wfc = (const float*)d_in[6];
    const float* bfc = (const float*)d_in[7];
    float*       out = (float*)d_out;

    int nN = in_sizes[0] / FIN;
    int nE = in_sizes[1] / 2;
    const int* rowI = ei;
    const int* colI = ei + nE;

    float *p_y1, *p_y2, *p_s2, *p_xw2;
    cudaGetSymbolAddress((void**)&p_y1,  g_y1);
    cudaGetSymbolAddress((void**)&p_y2,  g_y2);
    cudaGetSymbolAddress((void**)&p_s2,  g_s2);
    cudaGetSymbolAddress((void**)&p_xw2, g_xw2);

    // --- degree + CSR build (no prefix scan: global-cursor ranges) ---
    k_zero_deg <<<(nN + 255) / 256, 256>>>(nN);
    k_count_deg<<<(nE + 255) / 256, 256>>>(colI, nE);
    k_assign   <<<(nN + 255) / 256, 256>>>(nN);
    k_fill     <<<(nE + 255) / 256, 256>>>(rowI, colI, nE);

    // --- layer 1: y1 = d_r ⊙ (x @ W1) ---
    k_dense_w<FIN, H1, 4, 8, 8, 0, 1><<<(nN + 63) / 64, dim3(32, 8)>>>(
        x, W1, nullptr, p_y1, nN);

    // --- agg1 + mid fused: y2 = d ⊙ relu(d ⊙ (y1_self + Σ y1[src]) + b1) ---
    k_gather<C4_H1, 1><<<(nN + 7) / 8, dim3(32, 8)>>>(
        (const float4*)p_y1, b1, (float4*)p_y2, nN);

    // --- agg2 (commuted before GEMM): s2 = d ⊙ (y2_self + Σ y2[src]) ---
    k_gather<C4_H1, 2><<<(nN + 7) / 8, dim3(32, 8)>>>(
        (const float4*)p_y2, nullptr, (float4*)p_s2, nN);

    // --- layer 2 GEMM: xw2 = s2 @ W2 + b2 ---
    k_dense_w<H1, H2, 7, 8, 8, 0, 0><<<(nN + 63) / 64, dim3(32, 8)>>>(
        p_s2, W2, b2, p_xw2, nN);

    // --- FC: out = relu(xw2) @ Wfc + bfc ---
    k_dense<H2, FOUT, 8, 4, 1><<<(nN + 31) / 32, dim3(FOUT, 8)>>>(
        p_xw2, Wfc, bfc, out, nN);
}